// round 5
// baseline (speedup 1.0000x reference)
#include <cuda_runtime.h>

// B=1, H=16, S=4096, D=64, fp32, NO softmax.
// (Q K^T) V == Q (K^T V);  K^T V is [64x64] per head -> 64x fewer FLOPs.
// R4: f32x2 packed FFMA *with 256-thread blocks* (R3 lost occupancy, not the
// f32x2 bet). Thread tile = 2 rows (broadcast) x 8 cols (packed pairs).
#define HEADS 16
#define SEQ   4096
#define DIM   64
#define NSPLIT 32
#define CHUNK (SEQ / NSPLIT)   // 128 rows per partial block
#define STILE 64               // K/V rows staged in smem per phase

__device__ __align__(16) float g_partial[HEADS * NSPLIT * DIM * DIM];  // 8 MB
__device__ __align__(16) float g_M[HEADS * DIM * DIM];                 // 256 KB

// ---- f32x2 packed helpers -------------------------------------------------
__device__ __forceinline__ void ffma2(unsigned long long& acc,
                                      unsigned long long a,
                                      unsigned long long b) {
    asm("fma.rn.f32x2 %0, %1, %2, %0;" : "+l"(acc) : "l"(a), "l"(b));
}
__device__ __forceinline__ unsigned long long bcast2(float x) {
    unsigned long long r;
    asm("mov.b64 %0, {%1, %1};" : "=l"(r) : "f"(x));
    return r;
}

// ---------------------------------------------------------------------------
// Kernel 1: partial M = K_chunk^T @ V_chunk.  grid = HEADS*NSPLIT, 256 thr.
// Thread (ci,cj): rows 2*ci..2*ci+1 (ci=tid>>3, 0..31), cols 8*cj.. (cj=tid&7).
// ---------------------------------------------------------------------------
__global__ __launch_bounds__(256) void ktv_partial(const float* __restrict__ Kp,
                                                   const float* __restrict__ Vp) {
    const int h  = blockIdx.x / NSPLIT;
    const int sp = blockIdx.x % NSPLIT;
    const float* Kh = Kp + ((size_t)h * SEQ + (size_t)sp * CHUNK) * DIM;
    const float* Vh = Vp + ((size_t)h * SEQ + (size_t)sp * CHUNK) * DIM;

    __shared__ __align__(16) float Ks[STILE][DIM];   // 16 KB
    __shared__ __align__(16) float Vs[STILE][DIM];   // 16 KB

    const int tid = threadIdx.x;
    const int ci = tid >> 3;   // 0..31 -> K-dim rows 2*ci..
    const int cj = tid & 7;    // 0..7  -> V-dim cols 8*cj..

    unsigned long long acc[2][4] = {};   // 2 rows x 4 f32x2 (8 cols)

    for (int t = 0; t < CHUNK; t += STILE) {
        // cooperative load: STILE rows x 64 floats of K and V (1024 float4 each)
        #pragma unroll
        for (int i = tid; i < STILE * 16; i += 256) {
            const int r  = i >> 4;
            const int c4 = (i & 15) << 2;
            *(float4*)&Ks[r][c4] = *(const float4*)&Kh[(size_t)(t + r) * DIM + c4];
            *(float4*)&Vs[r][c4] = *(const float4*)&Vh[(size_t)(t + r) * DIM + c4];
        }
        __syncthreads();

        #pragma unroll
        for (int s = 0; s < STILE; s++) {
            const float2 kv = *(const float2*)&Ks[s][ci * 2];
            const ulonglong2 v01 = *(const ulonglong2*)&Vs[s][cj * 8];
            const ulonglong2 v23 = *(const ulonglong2*)&Vs[s][cj * 8 + 4];
            const unsigned long long vb[4] = {v01.x, v01.y, v23.x, v23.y};
            const unsigned long long ka0 = bcast2(kv.x);
            const unsigned long long ka1 = bcast2(kv.y);
            #pragma unroll
            for (int b = 0; b < 4; b++) ffma2(acc[0][b], ka0, vb[b]);
            #pragma unroll
            for (int b = 0; b < 4; b++) ffma2(acc[1][b], ka1, vb[b]);
        }
        __syncthreads();
    }

    float* outp = g_partial + ((size_t)h * NSPLIT + sp) * DIM * DIM;
    #pragma unroll
    for (int a = 0; a < 2; a++) {
        const int row = ci * 2 + a;
        *(ulonglong2*)&outp[row * DIM + cj * 8]     = make_ulonglong2(acc[a][0], acc[a][1]);
        *(ulonglong2*)&outp[row * DIM + cj * 8 + 4] = make_ulonglong2(acc[a][2], acc[a][3]);
    }
}

// ---------------------------------------------------------------------------
// Kernel 2: reduce NSPLIT partials -> g_M (float4-vectorized).
// ---------------------------------------------------------------------------
__global__ __launch_bounds__(256) void reduce_m() {
    const int idx = blockIdx.x * 256 + threadIdx.x;   // float4 index
    if (idx >= HEADS * DIM * DIM / 4) return;
    const int h = idx / (DIM * DIM / 4);
    const int e = idx % (DIM * DIM / 4);
    float4 s = make_float4(0.f, 0.f, 0.f, 0.f);
    #pragma unroll
    for (int p = 0; p < NSPLIT; p++) {
        const float4 t = *(const float4*)&g_partial[(((size_t)h * NSPLIT + p) * DIM * DIM) + e * 4];
        s.x += t.x; s.y += t.y; s.z += t.z; s.w += t.w;
    }
    *(float4*)&g_M[(size_t)idx * 4] = s;
}

// ---------------------------------------------------------------------------
// Kernel 3: out = Q @ M.  64 q-rows x 64 cols per block, 256 threads,
// thread (ci,cj): q-rows 2*ci.., out cols 8*cj..; Q tile transposed in smem.
// Pad row stride to 66 floats (264B): float2 loads at even offsets stay 8B-aligned.
// ---------------------------------------------------------------------------
#define QROWS 64
__global__ __launch_bounds__(256) void qm_gemm(const float* __restrict__ Qp,
                                               float* __restrict__ Op) {
    const int blocksPerHead = SEQ / QROWS;                 // 64
    const int h  = blockIdx.x / blocksPerHead;
    const int r0 = (blockIdx.x % blocksPerHead) * QROWS;

    __shared__ __align__(16) float Qt[DIM][QROWS + 2];   // Qt[k][row]
    __shared__ __align__(16) float Ms[DIM][DIM];

    const int tid = threadIdx.x;
    const float* Qh = Qp + ((size_t)h * SEQ + r0) * DIM;
    const float* Mh = g_M + (size_t)h * DIM * DIM;

    // load M (1024 float4, 4 per thread)
    #pragma unroll
    for (int i = tid; i < DIM * DIM / 4; i += 256) {
        const int r  = i >> 4;
        const int c4 = (i & 15) << 2;
        *(float4*)&Ms[r][c4] = *(const float4*)&Mh[r * DIM + c4];
    }
    // load Q tile, transpose into smem
    #pragma unroll
    for (int i = tid; i < QROWS * DIM / 4; i += 256) {
        const int r  = i >> 4;          // q-row 0..63
        const int c4 = (i & 15) << 2;   // k 0..60
        const float4 qv = *(const float4*)&Qh[(size_t)r * DIM + c4];
        Qt[c4 + 0][r] = qv.x;
        Qt[c4 + 1][r] = qv.y;
        Qt[c4 + 2][r] = qv.z;
        Qt[c4 + 3][r] = qv.w;
    }
    __syncthreads();

    const int ci = tid >> 3;   // 0..31 -> q rows 2*ci..
    const int cj = tid & 7;    // 0..7  -> out cols 8*cj..

    unsigned long long acc[2][4] = {};
    #pragma unroll
    for (int k = 0; k < DIM; k++) {
        const float2 qv = *(const float2*)&Qt[k][ci * 2];   // (66k+2ci)*4 % 8 == 0
        const ulonglong2 m01 = *(const ulonglong2*)&Ms[k][cj * 8];
        const ulonglong2 m23 = *(const ulonglong2*)&Ms[k][cj * 8 + 4];
        const unsigned long long mb[4] = {m01.x, m01.y, m23.x, m23.y};
        const unsigned long long qa0 = bcast2(qv.x);
        const unsigned long long qa1 = bcast2(qv.y);
        #pragma unroll
        for (int b = 0; b < 4; b++) ffma2(acc[0][b], qa0, mb[b]);
        #pragma unroll
        for (int b = 0; b < 4; b++) ffma2(acc[1][b], qa1, mb[b]);
    }

    float* Oh = Op + ((size_t)h * SEQ + r0) * DIM;
    #pragma unroll
    for (int a = 0; a < 2; a++) {
        const int row = ci * 2 + a;
        *(ulonglong2*)&Oh[(size_t)row * DIM + cj * 8]     = make_ulonglong2(acc[a][0], acc[a][1]);
        *(ulonglong2*)&Oh[(size_t)row * DIM + cj * 8 + 4] = make_ulonglong2(acc[a][2], acc[a][3]);
    }
}

// ---------------------------------------------------------------------------
extern "C" void kernel_launch(void* const* d_in, const int* in_sizes, int n_in,
                              void* d_out, int out_size) {
    const float* q = (const float*)d_in[0];
    const float* k = (const float*)d_in[1];
    const float* v = (const float*)d_in[2];
    float* out = (float*)d_out;

    ktv_partial<<<HEADS * NSPLIT, 256>>>(k, v);
    reduce_m<<<(HEADS * DIM * DIM / 4 + 255) / 256, 256>>>();
    qm_gemm<<<HEADS * (SEQ / QROWS), 256>>>(q, out);
}

// round 7
// speedup vs baseline: 2.2254x; 2.2254x over previous
#include <cuda_runtime.h>

// B=1, H=16, S=4096, D=64, fp32, NO softmax.
// (Q K^T) V == Q (K^T V);  K^T V is [64x64] per head -> 64x fewer FLOPs.
// R6: tensor cores. mma.sync.m16n8k8 tf32 with 3-term compensation (tf32x3):
//   x = hi + lo (both tf32);  A*B ~= Ah*Bh + Ah*Bl + Al*Bh  (fp32 accum)
// Precision ~ fp32 (lo*lo term ~2^-22 relative), so rel_err stays ~1e-6.
#define HEADS 16
#define SEQ   4096
#define DIM   64
#define NSPLIT 32
#define CHUNK (SEQ / NSPLIT)   // 128 rows per partial block

__device__ __align__(16) float g_partial[HEADS * NSPLIT * DIM * DIM];  // 8 MB
__device__ __align__(16) float g_M[HEADS * DIM * DIM];                 // 256 KB

// ---- tf32 helpers ---------------------------------------------------------
__device__ __forceinline__ void split_tf32(float x, unsigned& hi, unsigned& lo) {
    asm("cvt.rna.tf32.f32 %0, %1;" : "=r"(hi) : "f"(x));
    const float hf = __uint_as_float(hi);
    const float l  = x - hf;
    asm("cvt.rna.tf32.f32 %0, %1;" : "=r"(lo) : "f"(l));
}

__device__ __forceinline__ void mma_tf32(float* d, const unsigned* a, const unsigned* b) {
    asm("mma.sync.aligned.m16n8k8.row.col.f32.tf32.tf32.f32 "
        "{%0,%1,%2,%3}, {%4,%5,%6,%7}, {%8,%9}, {%0,%1,%2,%3};"
        : "+f"(d[0]), "+f"(d[1]), "+f"(d[2]), "+f"(d[3])
        : "r"(a[0]), "r"(a[1]), "r"(a[2]), "r"(a[3]), "r"(b[0]), "r"(b[1]));
}

// ---------------------------------------------------------------------------
// Kernel 1: partial M = K_chunk^T @ V_chunk.  grid = HEADS*NSPLIT, 256 thr.
// A = K^T (row=d1, col=s), B = V (row=s, col=d2).
// 8 warps: warp_m = wid&3 -> d1 block of 16; warp_n = wid>>2 -> d2 block of 32.
// smem row stride 72 floats: fragment gathers (t*8+g) are conflict-free.
// ---------------------------------------------------------------------------
#define KP 72
__global__ __launch_bounds__(256) void ktv_partial(const float* __restrict__ Kp,
                                                   const float* __restrict__ Vp) {
    const int h  = blockIdx.x / NSPLIT;
    const int sp = blockIdx.x % NSPLIT;
    const float* Kh = Kp + ((size_t)h * SEQ + (size_t)sp * CHUNK) * DIM;
    const float* Vh = Vp + ((size_t)h * SEQ + (size_t)sp * CHUNK) * DIM;

    __shared__ __align__(16) float Ks[64][KP];   // 18.4 KB
    __shared__ __align__(16) float Vs[64][KP];   // 18.4 KB

    const int tid  = threadIdx.x;
    const int wid  = tid >> 5;
    const int lane = tid & 31;
    const int g = lane >> 2;      // groupID 0..7
    const int t = lane & 3;       // threadID_in_group 0..3
    const int d1_0 = (wid & 3) * 16;
    const int d2_0 = (wid >> 2) * 32;

    float acc[4][4] = {};         // [ntile of 8 cols][c0..c3]

    for (int t0 = 0; t0 < CHUNK; t0 += 64) {
        // stage 64 rows x 64 floats of K and V (1024 float4 each)
        #pragma unroll
        for (int i = tid; i < 64 * 16; i += 256) {
            const int r  = i >> 4;
            const int c4 = (i & 15) << 2;
            *(float4*)&Ks[r][c4] = *(const float4*)&Kh[(size_t)(t0 + r) * DIM + c4];
            *(float4*)&Vs[r][c4] = *(const float4*)&Vh[(size_t)(t0 + r) * DIM + c4];
        }
        __syncthreads();

        #pragma unroll
        for (int ks = 0; ks < 64; ks += 8) {
            // A fragment: A[row=d1][col=s] = Ks[s][d1]
            const float a0f = Ks[ks + t][d1_0 + g];
            const float a1f = Ks[ks + t][d1_0 + g + 8];
            const float a2f = Ks[ks + t + 4][d1_0 + g];
            const float a3f = Ks[ks + t + 4][d1_0 + g + 8];
            unsigned ah[4], al[4];
            split_tf32(a0f, ah[0], al[0]);
            split_tf32(a1f, ah[1], al[1]);
            split_tf32(a2f, ah[2], al[2]);
            split_tf32(a3f, ah[3], al[3]);

            #pragma unroll
            for (int nt = 0; nt < 4; nt++) {
                const float b0f = Vs[ks + t][d2_0 + nt * 8 + g];
                const float b1f = Vs[ks + t + 4][d2_0 + nt * 8 + g];
                unsigned bh[2], bl[2];
                split_tf32(b0f, bh[0], bl[0]);
                split_tf32(b1f, bh[1], bl[1]);
                mma_tf32(acc[nt], ah, bh);
                mma_tf32(acc[nt], ah, bl);
                mma_tf32(acc[nt], al, bh);
            }
        }
        __syncthreads();
    }

    float* outp = g_partial + ((size_t)h * NSPLIT + sp) * DIM * DIM;
    #pragma unroll
    for (int nt = 0; nt < 4; nt++) {
        const int col = d2_0 + nt * 8 + 2 * t;
        const int row = d1_0 + g;
        *(float2*)&outp[row * DIM + col]       = make_float2(acc[nt][0], acc[nt][1]);
        *(float2*)&outp[(row + 8) * DIM + col] = make_float2(acc[nt][2], acc[nt][3]);
    }
}

// ---------------------------------------------------------------------------
// Kernel 2: reduce NSPLIT partials -> g_M (float4-vectorized).
// ---------------------------------------------------------------------------
__global__ __launch_bounds__(256) void reduce_m() {
    const int idx = blockIdx.x * 256 + threadIdx.x;   // float4 index
    if (idx >= HEADS * DIM * DIM / 4) return;
    const int h = idx / (DIM * DIM / 4);
    const int e = idx % (DIM * DIM / 4);
    float4 s = make_float4(0.f, 0.f, 0.f, 0.f);
    #pragma unroll
    for (int p = 0; p < NSPLIT; p++) {
        const float4 tv = *(const float4*)&g_partial[(((size_t)h * NSPLIT + p) * DIM * DIM) + e * 4];
        s.x += tv.x; s.y += tv.y; s.z += tv.z; s.w += tv.w;
    }
    *(float4*)&g_M[(size_t)idx * 4] = s;
}

// ---------------------------------------------------------------------------
// Kernel 3: out = Q @ M.  Block = 64 q-rows x 64 cols, 256 thr (8 warps).
// A = Q (row-major natural), B = M.
// smem row stride 68 floats: A-frag gathers (g*4+t) are conflict-free.
// ---------------------------------------------------------------------------
#define QP 68
__global__ __launch_bounds__(256) void qm_gemm(const float* __restrict__ Qp,
                                               float* __restrict__ Op) {
    const int h  = blockIdx.x >> 6;            // 64 blocks per head
    const int r0 = (blockIdx.x & 63) * 64;

    __shared__ __align__(16) float Qs[64][QP];   // 17.4 KB
    __shared__ __align__(16) float Ms[64][QP];   // 17.4 KB

    const int tid  = threadIdx.x;
    const int wid  = tid >> 5;
    const int lane = tid & 31;
    const int g = lane >> 2;
    const int t = lane & 3;
    const int rw   = (wid & 3) * 16;   // q-row block within the 64
    const int n0   = (wid >> 2) * 32;  // output col block of 32

    const float* Qh = Qp + ((size_t)h * SEQ + r0) * DIM;
    const float* Mh = g_M + (size_t)h * DIM * DIM;

    // stage Q tile and M (1024 float4 each)
    #pragma unroll
    for (int i = tid; i < 64 * 16; i += 256) {
        const int r  = i >> 4;
        const int c4 = (i & 15) << 2;
        *(float4*)&Qs[r][c4] = *(const float4*)&Qh[(size_t)r * DIM + c4];
        *(float4*)&Ms[r][c4] = *(const float4*)&Mh[r * DIM + c4];
    }
    __syncthreads();

    float acc[4][4] = {};

    #pragma unroll
    for (int ks = 0; ks < DIM; ks += 8) {
        const float a0f = Qs[rw + g][ks + t];
        const float a1f = Qs[rw + g + 8][ks + t];
        const float a2f = Qs[rw + g][ks + t + 4];
        const float a3f = Qs[rw + g + 8][ks + t + 4];
        unsigned ah[4], al[4];
        split_tf32(a0f, ah[0], al[0]);
        split_tf32(a1f, ah[1], al[1]);
        split_tf32(a2f, ah[2], al[2]);
        split_tf32(a3f, ah[3], al[3]);

        #pragma unroll
        for (int nt = 0; nt < 4; nt++) {
            const float b0f = Ms[ks + t][n0 + nt * 8 + g];
            const float b1f = Ms[ks + t + 4][n0 + nt * 8 + g];
            unsigned bh[2], bl[2];
            split_tf32(b0f, bh[0], bl[0]);
            split_tf32(b1f, bh[1], bl[1]);
            mma_tf32(acc[nt], ah, bh);
            mma_tf32(acc[nt], ah, bl);
            mma_tf32(acc[nt], al, bh);
        }
    }

    float* Oh = Op + ((size_t)h * SEQ + r0) * DIM;
    #pragma unroll
    for (int nt = 0; nt < 4; nt++) {
        const int col = n0 + nt * 8 + 2 * t;
        const int row = rw + g;
        *(float2*)&Oh[(size_t)row * DIM + col]       = make_float2(acc[nt][0], acc[nt][1]);
        *(float2*)&Oh[(size_t)(row + 8) * DIM + col] = make_float2(acc[nt][2], acc[nt][3]);
    }
}

// ---------------------------------------------------------------------------
extern "C" void kernel_launch(void* const* d_in, const int* in_sizes, int n_in,
                              void* d_out, int out_size) {
    const float* q = (const float*)d_in[0];
    const float* k = (const float*)d_in[1];
    const float* v = (const float*)d_in[2];
    float* out = (float*)d_out;

    ktv_partial<<<HEADS * NSPLIT, 256>>>(k, v);
    reduce_m<<<(HEADS * DIM * DIM / 4 + 255) / 256, 256>>>();
    qm_gemm<<<HEADS * (SEQ / DIM), 256>>>(q, out);
}